// round 15
// baseline (speedup 1.0000x reference)
#include <cuda_runtime.h>
#include <cstdint>

#define NMAX   100352          // >= N = 100000
#define CIN    128

// -------- scratch (no allocations allowed) --------
// alpha(e) = s_j[src] + s_i[dst]; per-src argmax is invariant under the constant
// s_j[src] offset. Key value is s_i[dst] only -> pack dst (not edge id) in the
// low bits; tie on exact-equal si breaks by min dst (duplicate edges unaffected).
__device__ float              g_Vi[CIN * 4];       // folded weight for s_i: [k][h]
__device__ float              g_si[NMAX * 4];      // s_i[n][h]
__device__ unsigned long long g_best[NMAX * 4];    // per (src, head): (ordf(si)<<32)|(0xFFFFFFFF-dst)
__device__ unsigned char      g_mask8[NMAX];       // node_mask bytes: 100KB, L1-resident, plain stores

// orderable-uint mapping for float (monotone)
__device__ __forceinline__ unsigned ordf(float f) {
    unsigned u = __float_as_uint(f);
    return (u & 0x80000000u) ? ~u : (u | 0x80000000u);
}
__device__ __forceinline__ unsigned long long make_key(float a, unsigned d) {
    return ((unsigned long long)ordf(a) << 32) | (unsigned long long)(0xFFFFFFFFu - d);
}

// -------- K1: fold weight+att into Vi (128x4) — tiny --------
__global__ __launch_bounds__(256) void k_init(const float* __restrict__ weight,
                                              const float* __restrict__ att) {
    int i = blockIdx.x * blockDim.x + threadIdx.x;
    if (i < 512) {
        int k = i >> 2;                // row of weight
        int h = i & 3;                 // head
        int base_att = h * 64 + 32;    // w_i half of att_weight
        const float* wrow = weight + k * CIN + h * 32;
        float s = 0.f;
        #pragma unroll
        for (int c = 0; c < 32; c++) s += wrow[c] * att[base_att + c];
        g_Vi[k * 4 + h] = s;
    }
}

// -------- K2: zero scratch + s_i = x @ Vi (zero-fill of x_out moved to k_argmax) --------
__global__ __launch_bounds__(256) void k_scores(const float* __restrict__ x, int N) {
    int t   = blockIdx.x * blockDim.x + threadIdx.x;
    int gsz = gridDim.x * blockDim.x;

    // zero best table + mask bytes (kernel boundary orders before argmax/winner)
    for (int i = t; i < N * 4; i += gsz) g_best[i] = 0ull;
    unsigned* m32 = (unsigned*)g_mask8;
    for (int i = t; i < NMAX / 4; i += gsz) m32[i] = 0u;

    int lane   = threadIdx.x & 31;
    int warpId = t >> 5;
    int nWarps = gsz >> 5;

    // each lane owns 4 rows of Vi (rows lane*4 .. lane*4+3), 4 cols each
    float4 Vi[4];
    #pragma unroll
    for (int r = 0; r < 4; r++)
        Vi[r] = ((const float4*)g_Vi)[lane * 4 + r];

    const float4* x4 = (const float4*)x;
    for (int n = warpId; n < N; n += nWarps) {
        // read-once stream: evict-first so edge arrays stay L2-resident
        float4 xv = __ldcs(&x4[(size_t)n * 32 + lane]);
        float acc[4];
        acc[0] = xv.x * Vi[0].x + xv.y * Vi[1].x + xv.z * Vi[2].x + xv.w * Vi[3].x;
        acc[1] = xv.x * Vi[0].y + xv.y * Vi[1].y + xv.z * Vi[2].y + xv.w * Vi[3].y;
        acc[2] = xv.x * Vi[0].z + xv.y * Vi[1].z + xv.z * Vi[2].z + xv.w * Vi[3].z;
        acc[3] = xv.x * Vi[0].w + xv.y * Vi[1].w + xv.z * Vi[2].w + xv.w * Vi[3].w;
        #pragma unroll
        for (int off = 16; off > 0; off >>= 1) {
            #pragma unroll
            for (int o = 0; o < 4; o++)
                acc[o] += __shfl_xor_sync(0xFFFFFFFFu, acc[o], off);
        }
        if (lane == 0)
            ((float4*)g_si)[n] = make_float4(acc[0], acc[1], acc[2], acc[3]);
    }
}

// -------- argmax core: ONE gather (si[d]) + read-before-atomic on packed keys --------
__device__ __forceinline__ void argmax_edge(int s, int d) {
    float4 si = ((const float4*)g_si)[d];
    unsigned long long k0 = make_key(si.x, (unsigned)d);
    unsigned long long k1 = make_key(si.y, (unsigned)d);
    unsigned long long k2 = make_key(si.z, (unsigned)d);
    unsigned long long k3 = make_key(si.w, (unsigned)d);
    unsigned long long* b = g_best + (size_t)s * 4;
    ulonglong2 p0 = *(const ulonglong2*)b;
    ulonglong2 p1 = *((const ulonglong2*)b + 1);
    // possibly-stale read only causes an extra (harmless) atomic
    if (k0 > p0.x) atomicMax(&b[0], k0);
    if (k1 > p0.y) atomicMax(&b[1], k1);
    if (k2 > p1.x) atomicMax(&b[2], k2);
    if (k3 > p1.y) atomicMax(&b[3], k3);
}

// -------- K3: per-edge argmax (4 edges/thread) + fused streaming zero-fill of x_out --------
// This kernel is L2-gather/atomic latency bound; its DRAM write bandwidth is idle.
// The fire-and-forget __stcs (evict-first) fill rides in that shadow without
// claiming L2 residency (edge arrays stay warm).
__global__ __launch_bounds__(256) void k_argmax_v4(const int* __restrict__ srcp,
                                                   const int* __restrict__ dstp,
                                                   float4* __restrict__ out_zero,
                                                   int zero_n4, int E) {
    int t   = blockIdx.x * blockDim.x + threadIdx.x;
    int gsz = gridDim.x * blockDim.x;

    float4 z = make_float4(0.f, 0.f, 0.f, 0.f);
    for (int i = t; i < zero_n4; i += gsz) __stcs(&out_zero[i], z);

    int e4 = t * 4;
    if (e4 >= E) return;
    int4 s4 = *(const int4*)(srcp + e4);
    int4 d4 = *(const int4*)(dstp + e4);
    argmax_edge(s4.x, d4.x);
    argmax_edge(s4.y, d4.y);
    argmax_edge(s4.z, d4.z);
    argmax_edge(s4.w, d4.w);
}

__global__ __launch_bounds__(256) void k_argmax_s(const int* __restrict__ srcp,
                                                  const int* __restrict__ dstp,
                                                  float4* __restrict__ out_zero,
                                                  int zero_n4, int E) {
    int t   = blockIdx.x * blockDim.x + threadIdx.x;
    int gsz = gridDim.x * blockDim.x;
    float4 z = make_float4(0.f, 0.f, 0.f, 0.f);
    for (int i = t; i < zero_n4; i += gsz) __stcs(&out_zero[i], z);
    if (t >= E) return;
    argmax_edge(srcp[t], dstp[t]);
}

// -------- K4: winner decode — dst in key; plain byte store (no atomics) --------
__global__ __launch_bounds__(256) void k_winner(int N4) {
    int i = blockIdx.x * blockDim.x + threadIdx.x;   // slot index in [0, N*4)
    if (i >= N4) return;
    unsigned long long key = __ldcs(&g_best[i]);     // coalesced, read-once
    // low 32 bits = 0xFFFFFFFF - dst; key==0 <=> empty segment
    if (key) g_mask8[0xFFFFFFFFu - (unsigned)key] = 1;  // benign race: all write 1
}

// -------- K5: edge_keep + node_mask + slices; mask probes hit the 100KB byte table --------
__global__ __launch_bounds__(256) void k_out_v4(const int* __restrict__ srcp,
                                                const int* __restrict__ dstp,
                                                const int* __restrict__ slices,
                                                float* __restrict__ out_keep,
                                                float* __restrict__ out_mask,
                                                float* __restrict__ out_slices,
                                                int E, int N) {
    int t  = blockIdx.x * blockDim.x + threadIdx.x;
    int i4 = t * 4;
    if (i4 < E) {
        int4 s4 = *(const int4*)(srcp + i4);
        int4 d4 = *(const int4*)(dstp + i4);
        float4 r;
        r.x = (g_mask8[s4.x] & g_mask8[d4.x]) ? 1.0f : 0.0f;
        r.y = (g_mask8[s4.y] & g_mask8[d4.y]) ? 1.0f : 0.0f;
        r.z = (g_mask8[s4.z] & g_mask8[d4.z]) ? 1.0f : 0.0f;
        r.w = (g_mask8[s4.w] & g_mask8[d4.w]) ? 1.0f : 0.0f;
        __stcs((float4*)(out_keep + i4), r);        // write-once, never re-read
    }
    if (i4 < N) {
        uchar4 mb = *(const uchar4*)(g_mask8 + i4); // coalesced 4-byte read
        float4 m;
        m.x = mb.x ? 1.0f : 0.0f;
        m.y = mb.y ? 1.0f : 0.0f;
        m.z = mb.z ? 1.0f : 0.0f;
        m.w = mb.w ? 1.0f : 0.0f;
        if (i4 + 3 < N) __stcs((float4*)(out_mask + i4), m);
        else {
            out_mask[i4] = m.x;
            if (i4 + 1 < N) out_mask[i4 + 1] = m.y;
            if (i4 + 2 < N) out_mask[i4 + 2] = m.z;
        }
    }
    if (t == 0) {
        out_slices[0] = (float)slices[0];
        out_slices[1] = (float)slices[1];
    }
}

__global__ __launch_bounds__(256) void k_out_s(const int* __restrict__ srcp,
                                               const int* __restrict__ dstp,
                                               const int* __restrict__ slices,
                                               float* __restrict__ out_keep,
                                               float* __restrict__ out_mask,
                                               float* __restrict__ out_slices,
                                               int E, int N) {
    int i = blockIdx.x * blockDim.x + threadIdx.x;
    if (i < E) out_keep[i] = (g_mask8[srcp[i]] & g_mask8[dstp[i]]) ? 1.0f : 0.0f;
    if (i < N) out_mask[i] = g_mask8[i] ? 1.0f : 0.0f;
    if (i == 0) {
        out_slices[0] = (float)slices[0];
        out_slices[1] = (float)slices[1];
    }
}

extern "C" void kernel_launch(void* const* d_in, const int* in_sizes, int n_in,
                              void* d_out, int out_size) {
    const float* x      = (const float*)d_in[0];
    const int*   eidx   = (const int*)d_in[1];
    const int*   slices = (const int*)d_in[2];
    const float* weight = (const float*)d_in[3];
    const float* att    = (const float*)d_in[4];

    int N = in_sizes[0] / CIN;
    int E = in_sizes[1] / 2;
    const int* srcp = eidx;
    const int* dstp = eidx + E;

    float* out = (float*)d_out;
    size_t xout_elems = (size_t)N * CIN;

    if ((size_t)out_size < xout_elems + (size_t)E + (size_t)N + 2) {
        cudaMemsetAsync(out, 0, (size_t)out_size * sizeof(float), 0);
        return;
    }

    float* out_keep   = out + xout_elems;
    float* out_mask   = out_keep + E;
    float* out_slices = out_mask + N;

    int zero_n4 = (int)(xout_elems / 4);            // CIN=128 -> divisible by 4
    bool vec_ok = ((E & 3) == 0);                   // int4 alignment of dstp/out_keep

    k_init<<<2, 256>>>(weight, att);
    k_scores<<<1568, 256>>>(x, N);

    if (vec_ok) {
        int blocks = (E / 4 + 255) / 256;           // 6.25M/4 threads covers edges; fill is grid-stride
        k_argmax_v4<<<blocks, 256>>>(srcp, dstp, (float4*)out, zero_n4, E);
    } else {
        k_argmax_s<<<(E + 255) / 256, 256>>>(srcp, dstp, (float4*)out, zero_n4, E);
    }

    k_winner<<<(N * 4 + 255) / 256, 256>>>(N * 4);

    if (vec_ok) {
        int m4 = ((E > N ? E : N) + 3) / 4;
        k_out_v4<<<(m4 + 255) / 256, 256>>>(srcp, dstp, slices, out_keep, out_mask, out_slices, E, N);
    } else {
        int m = (E > N) ? E : N;
        k_out_s<<<(m + 255) / 256, 256>>>(srcp, dstp, slices, out_keep, out_mask, out_slices, E, N);
    }
}

// round 16
// speedup vs baseline: 1.0111x; 1.0111x over previous
#include <cuda_runtime.h>
#include <cstdint>

#define NMAX   100352          // >= N = 100000
#define CIN    128

// -------- scratch (no allocations allowed) --------
// alpha(e) = s_j[src] + s_i[dst]; per-src argmax is invariant under the constant
// s_j[src] offset. Key value is s_i[dst] only -> pack dst (not edge id) in the
// low bits; tie on exact-equal si breaks by min dst (duplicate edges unaffected).
__device__ float              g_Vi[CIN * 4];       // folded weight for s_i: [k][h]
__device__ float              g_si[NMAX * 4];      // s_i[n][h]
__device__ unsigned long long g_best[NMAX * 4];    // per (src, head): (ordf(si)<<32)|(0xFFFFFFFF-dst)
__device__ unsigned char      g_mask8[NMAX];       // node_mask bytes: 100KB, L1-resident, plain stores

// orderable-uint mapping for float (monotone)
__device__ __forceinline__ unsigned ordf(float f) {
    unsigned u = __float_as_uint(f);
    return (u & 0x80000000u) ? ~u : (u | 0x80000000u);
}
__device__ __forceinline__ unsigned long long make_key(float a, unsigned d) {
    return ((unsigned long long)ordf(a) << 32) | (unsigned long long)(0xFFFFFFFFu - d);
}

// -------- K1: fold weight+att into Vi (128x4) — tiny --------
__global__ __launch_bounds__(256) void k_init(const float* __restrict__ weight,
                                              const float* __restrict__ att) {
    int i = blockIdx.x * blockDim.x + threadIdx.x;
    if (i < 512) {
        int k = i >> 2;                // row of weight
        int h = i & 3;                 // head
        int base_att = h * 64 + 32;    // w_i half of att_weight
        const float* wrow = weight + k * CIN + h * 32;
        float s = 0.f;
        #pragma unroll
        for (int c = 0; c < 32; c++) s += wrow[c] * att[base_att + c];
        g_Vi[k * 4 + h] = s;
    }
}

// -------- K2: zero scratch + s_i = x @ Vi (one warp/node, shuffle-reduce) --------
__global__ __launch_bounds__(256) void k_scores(const float* __restrict__ x, int N) {
    int t   = blockIdx.x * blockDim.x + threadIdx.x;
    int gsz = gridDim.x * blockDim.x;

    // zero best table + mask bytes (kernel boundary orders before argmax/winner)
    for (int i = t; i < N * 4; i += gsz) g_best[i] = 0ull;
    unsigned* m32 = (unsigned*)g_mask8;
    for (int i = t; i < NMAX / 4; i += gsz) m32[i] = 0u;

    int lane   = threadIdx.x & 31;
    int warpId = t >> 5;
    int nWarps = gsz >> 5;

    // each lane owns 4 rows of Vi (rows lane*4 .. lane*4+3), 4 cols each
    float4 Vi[4];
    #pragma unroll
    for (int r = 0; r < 4; r++)
        Vi[r] = ((const float4*)g_Vi)[lane * 4 + r];

    const float4* x4 = (const float4*)x;
    for (int n = warpId; n < N; n += nWarps) {
        // read-once stream: evict-first so edge arrays stay L2-resident
        float4 xv = __ldcs(&x4[(size_t)n * 32 + lane]);
        float acc[4];
        acc[0] = xv.x * Vi[0].x + xv.y * Vi[1].x + xv.z * Vi[2].x + xv.w * Vi[3].x;
        acc[1] = xv.x * Vi[0].y + xv.y * Vi[1].y + xv.z * Vi[2].y + xv.w * Vi[3].y;
        acc[2] = xv.x * Vi[0].z + xv.y * Vi[1].z + xv.z * Vi[2].z + xv.w * Vi[3].z;
        acc[3] = xv.x * Vi[0].w + xv.y * Vi[1].w + xv.z * Vi[2].w + xv.w * Vi[3].w;
        #pragma unroll
        for (int off = 16; off > 0; off >>= 1) {
            #pragma unroll
            for (int o = 0; o < 4; o++)
                acc[o] += __shfl_xor_sync(0xFFFFFFFFu, acc[o], off);
        }
        if (lane == 0)
            ((float4*)g_si)[n] = make_float4(acc[0], acc[1], acc[2], acc[3]);
    }
}

// -------- argmax core: ONE gather (si[d]) + read-before-atomic on packed keys --------
__device__ __forceinline__ void argmax_edge(int s, int d) {
    float4 si = ((const float4*)g_si)[d];
    unsigned long long k0 = make_key(si.x, (unsigned)d);
    unsigned long long k1 = make_key(si.y, (unsigned)d);
    unsigned long long k2 = make_key(si.z, (unsigned)d);
    unsigned long long k3 = make_key(si.w, (unsigned)d);
    unsigned long long* b = g_best + (size_t)s * 4;
    ulonglong2 p0 = *(const ulonglong2*)b;
    ulonglong2 p1 = *((const ulonglong2*)b + 1);
    // possibly-stale read only causes an extra (harmless) atomic
    if (k0 > p0.x) atomicMax(&b[0], k0);
    if (k1 > p0.y) atomicMax(&b[1], k1);
    if (k2 > p1.x) atomicMax(&b[2], k2);
    if (k3 > p1.y) atomicMax(&b[3], k3);
}

// -------- K3: per-edge argmax, 4 edges/thread via int4 (E % 4 == 0 path) --------
__global__ __launch_bounds__(256) void k_argmax_v4(const int* __restrict__ srcp,
                                                   const int* __restrict__ dstp, int E) {
    int e4 = (blockIdx.x * blockDim.x + threadIdx.x) * 4;
    if (e4 >= E) return;
    int4 s4 = *(const int4*)(srcp + e4);
    int4 d4 = *(const int4*)(dstp + e4);
    argmax_edge(s4.x, d4.x);
    argmax_edge(s4.y, d4.y);
    argmax_edge(s4.z, d4.z);
    argmax_edge(s4.w, d4.w);
}

__global__ __launch_bounds__(256) void k_argmax_s(const int* __restrict__ srcp,
                                                  const int* __restrict__ dstp, int E) {
    int e = blockIdx.x * blockDim.x + threadIdx.x;
    if (e >= E) return;
    argmax_edge(srcp[e], dstp[e]);
}

// -------- K4: winner decode + fused streaming zero-fill of x_out --------
// k_winner is the only kernel that is neither LTS- nor DRAM-saturated (measured:
// DRAM 4%, L2 19%, issue 4% — pure latency stalls). The 51MB evict-first fill
// rides in that shadow; __stcs does not claim L2 residency, so the edge arrays
// stay warm for k_out.
__global__ __launch_bounds__(256) void k_winner(float4* __restrict__ out_zero,
                                                int zero_n4, int N4) {
    int t   = blockIdx.x * blockDim.x + threadIdx.x;
    int gsz = gridDim.x * blockDim.x;

    if (t < N4) {
        unsigned long long key = __ldcs(&g_best[t]);     // coalesced, read-once
        // low 32 bits = 0xFFFFFFFF - dst; key==0 <=> empty segment
        if (key) g_mask8[0xFFFFFFFFu - (unsigned)key] = 1;  // benign race: all write 1
    }

    float4 z = make_float4(0.f, 0.f, 0.f, 0.f);
    for (int i = t; i < zero_n4; i += gsz) __stcs(&out_zero[i], z);
}

// -------- K5: edge_keep + node_mask + slices; mask probes hit the 100KB byte table --------
__global__ __launch_bounds__(256) void k_out_v4(const int* __restrict__ srcp,
                                                const int* __restrict__ dstp,
                                                const int* __restrict__ slices,
                                                float* __restrict__ out_keep,
                                                float* __restrict__ out_mask,
                                                float* __restrict__ out_slices,
                                                int E, int N) {
    int t  = blockIdx.x * blockDim.x + threadIdx.x;
    int i4 = t * 4;
    if (i4 < E) {
        int4 s4 = *(const int4*)(srcp + i4);
        int4 d4 = *(const int4*)(dstp + i4);
        float4 r;
        r.x = (g_mask8[s4.x] & g_mask8[d4.x]) ? 1.0f : 0.0f;
        r.y = (g_mask8[s4.y] & g_mask8[d4.y]) ? 1.0f : 0.0f;
        r.z = (g_mask8[s4.z] & g_mask8[d4.z]) ? 1.0f : 0.0f;
        r.w = (g_mask8[s4.w] & g_mask8[d4.w]) ? 1.0f : 0.0f;
        __stcs((float4*)(out_keep + i4), r);        // write-once, never re-read
    }
    if (i4 < N) {
        uchar4 mb = *(const uchar4*)(g_mask8 + i4); // coalesced 4-byte read
        float4 m;
        m.x = mb.x ? 1.0f : 0.0f;
        m.y = mb.y ? 1.0f : 0.0f;
        m.z = mb.z ? 1.0f : 0.0f;
        m.w = mb.w ? 1.0f : 0.0f;
        if (i4 + 3 < N) __stcs((float4*)(out_mask + i4), m);
        else {
            out_mask[i4] = m.x;
            if (i4 + 1 < N) out_mask[i4 + 1] = m.y;
            if (i4 + 2 < N) out_mask[i4 + 2] = m.z;
        }
    }
    if (t == 0) {
        out_slices[0] = (float)slices[0];
        out_slices[1] = (float)slices[1];
    }
}

__global__ __launch_bounds__(256) void k_out_s(const int* __restrict__ srcp,
                                               const int* __restrict__ dstp,
                                               const int* __restrict__ slices,
                                               float* __restrict__ out_keep,
                                               float* __restrict__ out_mask,
                                               float* __restrict__ out_slices,
                                               int E, int N) {
    int i = blockIdx.x * blockDim.x + threadIdx.x;
    if (i < E) out_keep[i] = (g_mask8[srcp[i]] & g_mask8[dstp[i]]) ? 1.0f : 0.0f;
    if (i < N) out_mask[i] = g_mask8[i] ? 1.0f : 0.0f;
    if (i == 0) {
        out_slices[0] = (float)slices[0];
        out_slices[1] = (float)slices[1];
    }
}

extern "C" void kernel_launch(void* const* d_in, const int* in_sizes, int n_in,
                              void* d_out, int out_size) {
    const float* x      = (const float*)d_in[0];
    const int*   eidx   = (const int*)d_in[1];
    const int*   slices = (const int*)d_in[2];
    const float* weight = (const float*)d_in[3];
    const float* att    = (const float*)d_in[4];

    int N = in_sizes[0] / CIN;
    int E = in_sizes[1] / 2;
    const int* srcp = eidx;
    const int* dstp = eidx + E;

    float* out = (float*)d_out;
    size_t xout_elems = (size_t)N * CIN;

    if ((size_t)out_size < xout_elems + (size_t)E + (size_t)N + 2) {
        cudaMemsetAsync(out, 0, (size_t)out_size * sizeof(float), 0);
        return;
    }

    float* out_keep   = out + xout_elems;
    float* out_mask   = out_keep + E;
    float* out_slices = out_mask + N;

    int zero_n4 = (int)(xout_elems / 4);            // CIN=128 -> divisible by 4
    bool vec_ok = ((E & 3) == 0);                   // int4 alignment of dstp/out_keep

    k_init<<<2, 256>>>(weight, att);
    k_scores<<<1568, 256>>>(x, N);

    if (vec_ok) k_argmax_v4<<<(E / 4 + 255) / 256, 256>>>(srcp, dstp, E);
    else        k_argmax_s<<<(E + 255) / 256, 256>>>(srcp, dstp, E);

    k_winner<<<(N * 4 + 255) / 256, 256>>>((float4*)out, zero_n4, N * 4);

    if (vec_ok) {
        int m4 = ((E > N ? E : N) + 3) / 4;
        k_out_v4<<<(m4 + 255) / 256, 256>>>(srcp, dstp, slices, out_keep, out_mask, out_slices, E, N);
    } else {
        int m = (E > N) ? E : N;
        k_out_s<<<(m + 255) / 256, 256>>>(srcp, dstp, slices, out_keep, out_mask, out_slices, E, N);
    }
}